// round 14
// baseline (speedup 1.0000x reference)
#include <cuda_runtime.h>
#include <cuda_bf16.h>
#include <cstdint>

// Problem constants
#define NB   16
#define NPTS 65536
#define NPAT 64      // NUM_PATCHES
#define KNN  32      // PATCH_SIZE

// FPS: 8 CTAs per batch, 1024 threads, 8 points per thread
#define FPS_BLKS   8
#define FPS_THR    1024
#define FPS_PPT    8

typedef unsigned long long u64;
typedef unsigned int u32;

// Scratch (allocation-free rule: __device__ globals)
__device__ float4 g_pts4[NB * NPTS];               // x,y,z,|p|^2 (FMA-chain p2)
__device__ u64    g_part[NB * NPAT * FPS_BLKS];    // per-(batch,iter,cta) argmax slot
__device__ u64    g_kpart[NB * NPAT * 4 * KNN];    // per-(center,quarter) sorted top-32
__device__ u32    g_cm[NB * NPAT];                 // shared pruning bound (flipped d2)

// ---- packed f32x2 helpers (per-lane RN => bit-identical to scalar) ----
__device__ __forceinline__ u64 pk2(float a, float b) {
    u64 r; asm("mov.b64 %0,{%1,%2};" : "=l"(r) : "f"(a), "f"(b)); return r;
}
__device__ __forceinline__ void upk2(u64 v, float& a, float& b) {
    asm("mov.b64 {%0,%1},%2;" : "=f"(a), "=f"(b) : "l"(v));
}
__device__ __forceinline__ u64 add2(u64 a, u64 b) {
    u64 r; asm("add.rn.f32x2 %0,%1,%2;" : "=l"(r) : "l"(a), "l"(b)); return r;
}
__device__ __forceinline__ u64 mul2(u64 a, u64 b) {
    u64 r; asm("mul.rn.f32x2 %0,%1,%2;" : "=l"(r) : "l"(a), "l"(b)); return r;
}

// ---- atomic helpers ----
__device__ __forceinline__ void red_min_u32(u32* p, u32 v) {
    asm volatile("red.relaxed.gpu.global.min.u32 [%0], %1;" :: "l"(p), "r"(v) : "memory");
}
__device__ __forceinline__ u32 ld_cg_u32(const u32* p) {
    u32 v; asm volatile("ld.global.cg.u32 %0, [%1];" : "=r"(v) : "l"(p) : "memory");
    return v;
}

// ---------------------------------------------------------------------------
// Kernel 0: prep — pad points to float4 with p2; zero FPS slots; init g_cm.
// p2 uses the XLA/LLVM FP-contraction shape: fma(z,z, fma(y,y, x*x)).
// Runs BEFORE fps/knn: kernel ordering publishes g_pts4/g_cm (no fences).
// ---------------------------------------------------------------------------
__global__ void prep_kernel(const float* __restrict__ pts) {
    int i = blockIdx.x * blockDim.x + threadIdx.x;   // 1,048,576 threads
    if (i < NB * NPAT * FPS_BLKS) g_part[i] = 0ull;
    if (i < NB * NPAT)            g_cm[i]  = 0xFFFFFFFFu;   // flipped(+inf)
    float x = pts[3 * i + 0];
    float y = pts[3 * i + 1];
    float z = pts[3 * i + 2];
    float p2 = __fmaf_rn(z, z, __fmaf_rn(y, y, __fmul_rn(x, x)));
    g_pts4[i] = make_float4(x, y, z, p2);
}

// ---------------------------------------------------------------------------
// Kernel 1: FPS — UNCHANGED from r10 (measured-best handshake family).
// 8 CTAs per batch, points+min_d in registers (packed f32x2, bit-exact),
// volatile L2 slots + parallel 8-lane tight poll + prefetched winner coords.
// ---------------------------------------------------------------------------
__global__ void __launch_bounds__(FPS_THR, 1)
fps_kernel(float* __restrict__ centers_out /* [NB][NPAT][3] */) {
    const int b    = blockIdx.y;
    const int sub  = blockIdx.x;          // 0..7
    const int tid  = threadIdx.x;
    const int lane = tid & 31;
    const int wid  = tid >> 5;            // 0..31

    const float4* pts = g_pts4 + (size_t)b * NPTS;
    volatile u64* part = (volatile u64*)(g_part + (size_t)b * NPAT * FPS_BLKS);
    const int gbase = sub * (NPTS / FPS_BLKS);   // 8192 per CTA

    u64 pxk[4], pyk[4], pzk[4];
    float md[FPS_PPT];
#pragma unroll
    for (int jj = 0; jj < 4; jj++) {
        float4 p0 = pts[gbase + (2 * jj) * FPS_THR + tid];
        float4 p1 = pts[gbase + (2 * jj + 1) * FPS_THR + tid];
        pxk[jj] = pk2(p0.x, p1.x);
        pyk[jj] = pk2(p0.y, p1.y);
        pzk[jj] = pk2(p0.z, p1.z);
        md[2 * jj] = 3.402823466e38f;      // finfo(float32).max
        md[2 * jj + 1] = 3.402823466e38f;
    }

    __shared__ float sc[4];
    __shared__ u64 wb[32];

    if (tid == 0) {   // deterministic start: point 0
        float4 c = pts[0];
        sc[0] = c.x; sc[1] = c.y; sc[2] = c.z;
    }

    for (int iter = 0; iter < NPAT; iter++) {
        __syncthreads();   // sc valid
        float cx = sc[0], cy = sc[1], cz = sc[2];
        if (sub == 0 && tid == 0) {
            centers_out[(b * NPAT + iter) * 3 + 0] = cx;
            centers_out[(b * NPAT + iter) * 3 + 1] = cy;
            centers_out[(b * NPAT + iter) * 3 + 2] = cz;
        }
        if (iter == NPAT - 1) break;   // last winner never consumed

        // --- packed update + argmax (bit-exact vs scalar non-fused chain) ---
        u64 ncx = pk2(-cx, -cx), ncy = pk2(-cy, -cy), ncz = pk2(-cz, -cz);
        float bestv = -1.0f;
        u32   besti = 0;
#pragma unroll
        for (int jj = 0; jj < 4; jj++) {
            u64 dx = add2(pxk[jj], ncx);
            u64 dy = add2(pyk[jj], ncy);
            u64 dz = add2(pzk[jj], ncz);
            u64 s  = add2(add2(mul2(dx, dx), mul2(dy, dy)), mul2(dz, dz));
            float d0, d1; upk2(s, d0, d1);
            u32 gi0 = (u32)(gbase + 2 * jj * FPS_THR + tid);
            float m0 = fminf(md[2 * jj], d0);     md[2 * jj] = m0;
            if (m0 > bestv) { bestv = m0; besti = gi0; }
            float m1 = fminf(md[2 * jj + 1], d1); md[2 * jj + 1] = m1;
            if (m1 > bestv) { bestv = m1; besti = gi0 + FPS_THR; }
        }
        // key: (d bits, ~idx) -> max == argmax, ties -> lowest index; key > 0
        u64 key = ((u64)__float_as_uint(bestv) << 32) | (u32)(~besti);
#pragma unroll
        for (int off = 16; off; off >>= 1) {
            u64 o = __shfl_xor_sync(0xffffffffu, key, off);
            if (o > key) key = o;
        }
        if (lane == 0) wb[wid] = key;
        __syncthreads();
        if (wid == 0) {
            u64 v = wb[lane];
#pragma unroll
            for (int off = 16; off; off >>= 1) {
                u64 o = __shfl_xor_sync(0xffffffffu, v, off);
                if (o > v) v = o;
            }
            if (lane == 0) part[iter * FPS_BLKS + sub] = v;   // volatile store
            if (lane < FPS_BLKS) {
                u64 s;
                while ((s = part[iter * FPS_BLKS + lane]) == 0ull) {}  // tight poll
                u32 cand = ~(u32)s;
                float4 pc = pts[cand];        // prefetch candidate coords (L2)
                u64 m = s;
#pragma unroll
                for (int off = 4; off; off >>= 1) {
                    u64 o = __shfl_xor_sync(0xffu, m, off);
                    if (o > m) m = o;
                }
                u32 bal = __ballot_sync(0xffu, s == m);
                int src = __ffs(bal) - 1;     // winner's poller lane
                float wx = __shfl_sync(0xffu, pc.x, src);
                float wy = __shfl_sync(0xffu, pc.y, src);
                float wz = __shfl_sync(0xffu, pc.z, src);
                if (lane == 0) { sc[0] = wx; sc[1] = wy; sc[2] = wz; }
            }
        }
    }
}

// ---------------------------------------------------------------------------
// Kernel 2: exact KNN top-32. 512 blocks x 256 thr (launch_bounds(256,6) ->
// 48 warps/SM, single wave). Block = (8 centers) x (1 quarter); ONE warp per
// (center, quarter) scans 16384 pts -> fewer warm-up accepts than 8-way split.
// Shared pruning bound g_cm[center]: any warp's 32nd-smallest is an upper
// bound on the global 32nd, so gating with min(local, global) is exact.
// Gate + insert logic byte-identical to r10 (validated exact).
// ---------------------------------------------------------------------------
__device__ __forceinline__ u64 bsort32(u64 v, int lane) {
#pragma unroll
    for (int k = 2; k <= 32; k <<= 1) {
#pragma unroll
        for (int j = k >> 1; j > 0; j >>= 1) {
            u64 o = __shfl_xor_sync(0xffffffffu, v, j);
            bool up      = ((lane & k) == 0);
            bool keepmin = (((lane & j) == 0) == up);
            bool smaller = (v < o);
            v = (smaller == keepmin) ? v : o;
        }
    }
    return v;
}
__device__ __forceinline__ u64 bmerge32(u64 v, int lane) {
#pragma unroll
    for (int j = 16; j > 0; j >>= 1) {
        u64 o = __shfl_xor_sync(0xffffffffu, v, j);
        bool keepmin = ((lane & j) == 0);
        bool smaller = (v < o);
        v = (smaller == keepmin) ? v : o;
    }
    return v;
}
__device__ __forceinline__ u32 flipf(float f) {
    u32 u = __float_as_uint(f);
    return u ^ ((u & 0x80000000u) ? 0xFFFFFFFFu : 0x80000000u);
}
__device__ __forceinline__ float unflipf(u32 u) {
    u ^= (u & 0x80000000u) ? 0x80000000u : 0xFFFFFFFFu;
    return __uint_as_float(u);
}

#define KCH  512             // points staged per chunk
#define QTRP (NPTS / 4)      // 16384 points per quarter

__global__ void __launch_bounds__(256, 6)
knn_kernel(const float* __restrict__ centers /* [NB][NPAT][3] */) {
    const int b    = blockIdx.y;          // 16
    const int q    = blockIdx.x & 3;      // point quarter 0..3
    const int grp  = blockIdx.x >> 2;     // center group 0..7
    const int tid  = threadIdx.x;
    const int lane = tid & 31;
    const int w    = tid >> 5;            // 0..7 == center within group
    const int c    = grp * 8 + w;
    const int bc   = b * NPAT + c;

    const float4* pbase = g_pts4 + (size_t)b * NPTS;

    const float cx = centers[bc * 3 + 0];
    const float cy = centers[bc * 3 + 1];
    const float cz = centers[bc * 3 + 2];
    const float c2 = __fmaf_rn(cz, cz, __fmaf_rn(cy, cy, __fmul_rn(cx, cx)));

    u64 L = 0xFF80000000000000ull;              // key for d2=+inf, idx 0
    float cm = __int_as_float(0x7f800000);      // +inf
    float lastpub = cm;

    __shared__ float4 chunk[KCH];               // 8 KB

    const int qbase = q * QTRP;

    for (int cb = 0; cb < QTRP; cb += KCH) {
        __syncthreads();
        for (int t = tid; t < KCH; t += 256) chunk[t] = pbase[qbase + cb + t];
        __syncthreads();

        // refresh shared bound (conservative if stale; exactness unaffected)
        {
            u32 g = 0xFFFFFFFFu;
            if (lane == 0) g = ld_cg_u32(&g_cm[bc]);
            g = __shfl_sync(0xffffffffu, g, 0);
            cm = fminf(cm, unflipf(g));
        }

#pragma unroll 1
        for (int i = 0; i < KCH / 128; i++) {
            float d2[4];
#pragma unroll
            for (int k = 0; k < 4; k++) {
                float4 v = chunk[i * 128 + k * 32 + lane];
                // XLA-shape d2: fma(-2, dot, c2+p2), dot = fma chain
                float dot = __fmaf_rn(v.z, cz, __fmaf_rn(v.y, cy, __fmul_rn(v.x, cx)));
                d2[k] = __fmaf_rn(-2.0f, dot, __fadd_rn(c2, v.w));
            }
            float mn = fminf(fminf(d2[0], d2[1]), fminf(d2[2], d2[3]));
            if (__any_sync(0xffffffffu, mn <= cm)) {
#pragma unroll
                for (int k = 0; k < 4; k++) {
                    u32 mask = __ballot_sync(0xffffffffu, d2[k] <= cm);
                    if (!mask) continue;
                    u64 cand = ((u64)flipf(d2[k]) << 32)
                             | (u32)(qbase + cb + i * 128 + k * 32 + lane);
                    if (__popc(mask) <= 8) {
                        while (mask) {
                            int src = __ffs(mask) - 1; mask &= mask - 1;
                            u64 kk = __shfl_sync(0xffffffffu, cand, src);
                            u64 up = __shfl_up_sync(0xffffffffu, L, 1);
                            if (lane == 0) up = kk;
                            u64 mx = (kk > up) ? kk : up;
                            L = (L < kk) ? L : mx;
                        }
                    } else {
                        u64 cs = bsort32(cand, lane);
                        u64 o  = __shfl_sync(0xffffffffu, cs, 31 - lane);
                        u64 m  = (L < o) ? L : o;
                        L = bmerge32(m, lane);
                    }
                    u64 top = __shfl_sync(0xffffffffu, L, 31);
                    cm = fminf(cm, unflipf((u32)(top >> 32)));
                }
            }
        }
        // publish improved bound (relaxed: monotonic refinement)
        if (lane == 0 && cm < lastpub) {
            red_min_u32(&g_cm[bc], flipf(cm));
            lastpub = cm;
        }
    }

    // write this (center, quarter)'s sorted top-32 partial
    g_kpart[((size_t)bc * 4 + q) * KNN + lane] = L;
}

// ---------------------------------------------------------------------------
// Kernel 3: merge the 4 quarter-partials per center (exact bitonic set-merge),
// gather neighbors, subtract center. One center per warp.
// ---------------------------------------------------------------------------
__global__ void __launch_bounds__(256, 4)
merge_kernel(const float* __restrict__ centers,
             float* __restrict__ patches_out /* [NB][NPAT][KNN][3] */) {
    const int b    = blockIdx.x >> 3;     // 16
    const int grp  = blockIdx.x & 7;      // 8
    const int tid  = threadIdx.x;
    const int lane = tid & 31;
    const int w    = tid >> 5;            // 0..7
    const int c    = grp * 8 + w;

    const float4* pbase = g_pts4 + (size_t)b * NPTS;

    const u64* lists = g_kpart + ((size_t)(b * NPAT + c)) * 4 * KNN;
    u64 L = lists[lane];
#pragma unroll
    for (int j = 1; j < 4; j++) {
        u64 o = lists[j * KNN + (31 - lane)];
        u64 m = (L < o) ? L : o;
        L = bmerge32(m, lane);
    }
    const float cx = centers[(b * NPAT + c) * 3 + 0];
    const float cy = centers[(b * NPAT + c) * 3 + 1];
    const float cz = centers[(b * NPAT + c) * 3 + 2];
    u32 gi = (u32)L;
    float4 p = pbase[gi];
    float* dst = patches_out + ((size_t)(b * NPAT + c) * KNN + lane) * 3;
    dst[0] = p.x - cx;
    dst[1] = p.y - cy;
    dst[2] = p.z - cz;
}

// ---------------------------------------------------------------------------
// Launch: prep -> fps -> knn -> merge. Graph-capturable, alloc-free.
// Replay-safe: prep re-zeroes g_part and re-inits g_cm at the START of every
// replay; g_kpart fully rewritten before merge reads it.
// Output: tuple(patches, centers): [NB*NPAT*KNN*3] then [NB*NPAT*3]
// ---------------------------------------------------------------------------
extern "C" void kernel_launch(void* const* d_in, const int* in_sizes, int n_in,
                              void* d_out, int out_size) {
    const float* pts = (const float*)d_in[0];
    float* out      = (float*)d_out;
    float* patches  = out;                               // 16*64*32*3 = 98304
    float* centers  = out + (size_t)NB * NPAT * KNN * 3; // 16*64*3   =  3072

    prep_kernel<<<4096, 256>>>(pts);
    fps_kernel<<<dim3(FPS_BLKS, NB), FPS_THR>>>(centers);
    knn_kernel<<<dim3(32, NB), 256>>>(centers);
    merge_kernel<<<128, 256>>>(centers, patches);
}